// round 1
// baseline (speedup 1.0000x reference)
#include <cuda_runtime.h>
#include <cuda_bf16.h>

// ============================================================================
// NonLocalPositionAttention
//   y = alpha * (x @ softmax(e1^T e2)^T) + relu(w3 @ x + b3)
// with alpha == 0 for the benchmark inputs -> y == relu(w3 @ x + b3).
// The attention branch is implemented (correct for any alpha) but all its
// kernels early-exit on a device-side read of alpha when alpha == 0.
// ============================================================================

#define NB   4
#define CCH  2048
#define DCH  256
#define HW   4096

// ---- scratch for the (normally skipped) attention path --------------------
__device__ float g_e1[(size_t)NB * DCH * HW];                 // 16 MB
__device__ float g_e2[(size_t)NB * DCH * HW];                 // 16 MB
__device__ float g_attn[(size_t)NB * HW * HW];                // 256 MB

// ---- f32x2 helpers (FFMA2 path, sm_103a) ----------------------------------
__device__ __forceinline__ unsigned long long pack2(float lo, float hi) {
    unsigned long long r;
    asm("mov.b64 %0, {%1, %2};" : "=l"(r) : "f"(lo), "f"(hi));
    return r;
}
__device__ __forceinline__ void unpack2(unsigned long long v, float& lo, float& hi) {
    asm("mov.b64 {%0, %1}, %2;" : "=f"(lo), "=f"(hi) : "l"(v));
}
__device__ __forceinline__ unsigned long long fma2(unsigned long long a,
                                                   unsigned long long b,
                                                   unsigned long long c) {
    unsigned long long d;
    asm("fma.rn.f32x2 %0, %1, %2, %3;" : "=l"(d) : "l"(a), "l"(b), "l"(c));
    return d;
}

// ============================================================================
// Tiled SGEMM with bias + relu:
//   out[n, o, p] = relu( sum_c W[o, c] * X[n, c, p] + bias[o] )
// BM=128, BN=128, BK=16, 256 threads, 8x8 microtile, FFMA2 inner loop.
// A tile stored in SMEM pre-duplicated as {v,v} pairs so the inner loop is
// LDS.128 + FFMA2 only.
// ============================================================================
#define BM 128
#define BN 128
#define BK 16
#define APITCH 130   // ull units per kk-row (even pitch: keeps 16B alignment)

__global__ __launch_bounds__(256, 2)
void gemm_bias_relu(const float* __restrict__ W, const float* __restrict__ X,
                    const float* __restrict__ bias, float* __restrict__ out,
                    int O, int K, int P, const float* __restrict__ guard)
{
    if (guard != nullptr && __ldg(guard) == 0.0f) return;

    const int n  = blockIdx.z;
    const float* Xb = X  + (size_t)n * K * P;
    float*       Ob = out + (size_t)n * O * P;

    __shared__ unsigned long long As[BK * APITCH];  // duplicated {v,v} pairs
    __shared__ float              Bs[BK * BN];

    const int tid = threadIdx.x;
    const int tx  = tid & 15;   // n direction (8 cols each)
    const int ty  = tid >> 4;   // m direction (8 rows each)
    const int o0  = blockIdx.y * BM;
    const int p0  = blockIdx.x * BN;

    unsigned long long acc[8][4];
    #pragma unroll
    for (int i = 0; i < 8; ++i)
        #pragma unroll
        for (int j = 0; j < 4; ++j) acc[i][j] = 0ULL;

    // W-tile load mapping: 128x16 floats = 512 float4; thread t does f=t, t+256
    const int wr0 = tid >> 2;            // row within tile (for f = tid)
    const int wc0 = (tid & 3) * 4;       // col (k) within tile
    // X-tile load mapping: 16x128 floats = 512 float4
    const int xk0 = tid >> 5;            // k row within tile
    const int xc0 = (tid & 31) * 4;      // col (p) within tile

    for (int k0 = 0; k0 < K; k0 += BK) {
        // ---- load W tile (transposed + duplicated into As) ----
        #pragma unroll
        for (int l = 0; l < 2; ++l) {
            const int r = wr0 + l * 64;
            const float4 v = *reinterpret_cast<const float4*>(
                &W[(size_t)(o0 + r) * K + k0 + wc0]);
            As[(wc0 + 0) * APITCH + r] = pack2(v.x, v.x);
            As[(wc0 + 1) * APITCH + r] = pack2(v.y, v.y);
            As[(wc0 + 2) * APITCH + r] = pack2(v.z, v.z);
            As[(wc0 + 3) * APITCH + r] = pack2(v.w, v.w);
        }
        // ---- load X tile ----
        #pragma unroll
        for (int l = 0; l < 2; ++l) {
            const int kk = xk0 + l * 8;
            const float4 v = *reinterpret_cast<const float4*>(
                &Xb[(size_t)(k0 + kk) * P + p0 + xc0]);
            *reinterpret_cast<float4*>(&Bs[kk * BN + xc0]) = v;
        }
        __syncthreads();

        #pragma unroll
        for (int kk = 0; kk < BK; ++kk) {
            unsigned long long a[8];
            const unsigned long long* arow = &As[kk * APITCH + ty * 8];
            #pragma unroll
            for (int i = 0; i < 8; ++i) a[i] = arow[i];

            unsigned long long b[4];
            const unsigned long long* brow =
                reinterpret_cast<const unsigned long long*>(&Bs[kk * BN]) + tx * 4;
            #pragma unroll
            for (int j = 0; j < 4; ++j) b[j] = brow[j];

            #pragma unroll
            for (int i = 0; i < 8; ++i)
                #pragma unroll
                for (int j = 0; j < 4; ++j)
                    acc[i][j] = fma2(a[i], b[j], acc[i][j]);
        }
        __syncthreads();
    }

    // ---- epilogue: bias + relu ----
    #pragma unroll
    for (int i = 0; i < 8; ++i) {
        const int o = o0 + ty * 8 + i;
        const float bv = __ldg(&bias[o]);
        float* orow = &Ob[(size_t)o * P + p0 + tx * 8];
        #pragma unroll
        for (int j = 0; j < 4; ++j) {
            float lo, hi;
            unpack2(acc[i][j], lo, hi);
            float2 r;
            r.x = fmaxf(lo + bv, 0.0f);
            r.y = fmaxf(hi + bv, 0.0f);
            *reinterpret_cast<float2*>(&orow[2 * j]) = r;
        }
    }
}

// ============================================================================
// Attention fallback (only runs if alpha != 0): scores + softmax rows
//   attn[n, i, j] = softmax_j( sum_d e1[n,d,i] * e2[n,d,j] )
// One block processes multiple rows (grid kept small for cheap early-exit).
// ============================================================================
__global__ __launch_bounds__(256)
void attn_softmax_kernel(const float* __restrict__ alpha)
{
    if (__ldg(alpha) == 0.0f) return;

    __shared__ float e1col[DCH];
    __shared__ float red[256];
    const int tid = threadIdx.x;

    for (int row = blockIdx.x; row < NB * HW; row += gridDim.x) {
        const int n = row >> 12;
        const int i = row & (HW - 1);
        const float* e1n = g_e1 + (size_t)n * DCH * HW;
        const float* e2n = g_e2 + (size_t)n * DCH * HW;
        float* arow = g_attn + (size_t)n * HW * HW + (size_t)i * HW;

        e1col[tid] = e1n[(size_t)tid * HW + i];
        __syncthreads();

        float sc[16];
        float mx = -3.4e38f;
        #pragma unroll 1
        for (int jj = 0; jj < 16; ++jj) {
            const int j = jj * 256 + tid;
            float s = 0.0f;
            for (int d = 0; d < DCH; ++d) s += e1col[d] * e2n[(size_t)d * HW + j];
            sc[jj] = s;
            mx = fmaxf(mx, s);
        }
        // block-reduce max
        red[tid] = mx; __syncthreads();
        for (int s = 128; s > 0; s >>= 1) {
            if (tid < s) red[tid] = fmaxf(red[tid], red[tid + s]);
            __syncthreads();
        }
        mx = red[0]; __syncthreads();

        float sum = 0.0f;
        #pragma unroll
        for (int jj = 0; jj < 16; ++jj) { sc[jj] = expf(sc[jj] - mx); sum += sc[jj]; }
        red[tid] = sum; __syncthreads();
        for (int s = 128; s > 0; s >>= 1) {
            if (tid < s) red[tid] += red[tid + s];
            __syncthreads();
        }
        const float inv = 1.0f / red[0];
        __syncthreads();

        #pragma unroll
        for (int jj = 0; jj < 16; ++jj) arow[jj * 256 + tid] = sc[jj] * inv;
        __syncthreads();  // before e1col is overwritten for next row
    }
}

// ============================================================================
// Attention fallback bmm (only runs if alpha != 0):
//   out[n, c, i] += alpha * sum_j x[n, c, j] * attn[n, i, j]
// out already contains assembly.
// ============================================================================
__global__ __launch_bounds__(256)
void bmm_alpha_kernel(const float* __restrict__ x, float* __restrict__ out,
                      const float* __restrict__ alpha_p)
{
    const float alpha = __ldg(alpha_p);
    if (alpha == 0.0f) return;

    __shared__ float xs[HW];
    const int tid = threadIdx.x;

    for (int row = blockIdx.x; row < NB * CCH; row += gridDim.x) {
        const int n = row >> 11;
        const int c = row & (CCH - 1);
        const float* xr = x + ((size_t)n * CCH + c) * HW;
        const float* an = g_attn + (size_t)n * HW * HW;
        float* orow = out + ((size_t)n * CCH + c) * HW;

        for (int j = tid; j < HW; j += 256) xs[j] = xr[j];
        __syncthreads();

        for (int i = tid; i < HW; i += 256) {
            float acc = 0.0f;
            const float* ai = an + (size_t)i * HW;
            for (int j = 0; j < HW; ++j) acc += xs[j] * ai[j];
            orow[i] += alpha * acc;
        }
        __syncthreads();
    }
}

// ============================================================================
// launch
// ============================================================================
extern "C" void kernel_launch(void* const* d_in, const int* in_sizes, int n_in,
                              void* d_out, int out_size)
{
    const float* x     = (const float*)d_in[0];
    const float* w1    = (const float*)d_in[1];
    const float* b1    = (const float*)d_in[2];
    const float* w2    = (const float*)d_in[3];
    const float* b2    = (const float*)d_in[4];
    const float* w3    = (const float*)d_in[5];
    const float* b3    = (const float*)d_in[6];
    const float* alpha = (const float*)d_in[7];
    float* out = (float*)d_out;

    float *e1p = nullptr, *e2p = nullptr;
    cudaGetSymbolAddress((void**)&e1p, g_e1);
    cudaGetSymbolAddress((void**)&e2p, g_e2);

    dim3 blk(256);

    // assembly = relu(w3 @ x + b3) -> d_out   (always runs, dominant cost)
    gemm_bias_relu<<<dim3(HW / BN, CCH / BM, NB), blk>>>(
        w3, x, b3, out, CCH, CCH, HW, nullptr);

    // --- attention path: all guarded, early-exit when alpha == 0 ---
    gemm_bias_relu<<<dim3(HW / BN, DCH / BM, NB), blk>>>(
        w1, x, b1, e1p, DCH, CCH, HW, alpha);
    gemm_bias_relu<<<dim3(HW / BN, DCH / BM, NB), blk>>>(
        w2, x, b2, e2p, DCH, CCH, HW, alpha);
    attn_softmax_kernel<<<2048, blk>>>(alpha);
    bmm_alpha_kernel<<<1024, blk>>>(x, out, alpha);
}

// round 3
// speedup vs baseline: 3.5144x; 3.5144x over previous
#include <cuda_runtime.h>
#include <cuda_bf16.h>
#include <cstdint>

// ============================================================================
// NonLocalPositionAttention
//   y = alpha * (x @ softmax(e1^T e2)^T) + relu(w3 @ x + b3)
// alpha == 0 for benchmark inputs -> y == relu(w3 @ x + b3).
// Assembly GEMM runs on tensor cores via legacy mma.sync (tf32) — tcgen05 PTX
// is rejected by this toolchain (virtual arch compute_103, no 'a' features).
// Attention branch fully implemented but guarded (early-exit on alpha == 0).
// ============================================================================

#define NB   4
#define CCH  2048
#define DCH  256
#define HWP  4096

// ---- scratch for the (normally skipped) attention path --------------------
__device__ float g_e1[(size_t)NB * DCH * HWP];
__device__ float g_e2[(size_t)NB * DCH * HWP];
__device__ float g_attn[(size_t)NB * HWP * HWP];

// ============================================================================
// helpers
// ============================================================================
__device__ __forceinline__ uint32_t f2tf32(float x) {
    uint32_t u;
    asm("cvt.rna.tf32.f32 %0, %1;" : "=r"(u) : "f"(x));
    return u;
}

__device__ __forceinline__ void mma16n8k8(float* d, const uint32_t* a,
                                          const uint32_t* b) {
    asm volatile(
        "mma.sync.aligned.m16n8k8.row.col.f32.tf32.tf32.f32 "
        "{%0,%1,%2,%3}, {%4,%5,%6,%7}, {%8,%9}, {%0,%1,%2,%3};"
        : "+f"(d[0]), "+f"(d[1]), "+f"(d[2]), "+f"(d[3])
        : "r"(a[0]), "r"(a[1]), "r"(a[2]), "r"(a[3]), "r"(b[0]), "r"(b[1]));
}

// ============================================================================
// Tensor-core tf32 GEMM + bias + relu:
//   out[n,o,p] = relu( sum_c W[o,c] * X[n,c,p] + bias[o] )
// CTA tile: 128(m) x 128(n) x 32(k). 8 warps as 4(m) x 2(n); warp tile 32x64.
// A tile: stored in mma-fragment order (LDS.128 per frag), pitch-skewed.
// B tile: k x n rows, pitch 136 floats (conflict-free b-frag LDS.32).
// Single SMEM buffer; next slab's GMEM prefetched into registers.
// ============================================================================
#define TM 128
#define TN 128
#define TKK 32
#define NSLABS (CCH / TKK)     // 64
#define BPITCH 136             // floats per B row

__global__ void __launch_bounds__(256)
gemm_mma_bias_relu(const float* __restrict__ W, const float* __restrict__ X,
                   const float* __restrict__ bias, float* __restrict__ out)
{
    // A frag store: blocks (mt 0..7, ks 0..3), each 33 uint4 (32 lanes + skew)
    __shared__ uint32_t As[32 * 33 * 4];   // 16.9 KB
    __shared__ uint32_t Bs[TKK * BPITCH];  // 17.4 KB

    const int tid = threadIdx.x;
    const int wid = tid >> 5;
    const int lane = tid & 31;
    const int g   = lane >> 2;   // group id (0..7)
    const int tig = lane & 3;    // thread in group

    const int wm = wid >> 1;     // warp m position (0..3)
    const int wn = wid & 1;      // warp n position (0..1)

    const int n  = blockIdx.z;
    const int o0 = blockIdx.y * TM;
    const int p0 = blockIdx.x * TN;
    const float* Xb = X + (size_t)n * CCH * HWP;
    float*       Ob = out + (size_t)n * CCH * HWP;

    // accumulators: 2 m16 tiles x 8 n8 tiles x 4 floats
    float acc[2][8][4];
    #pragma unroll
    for (int mi = 0; mi < 2; ++mi)
        #pragma unroll
        for (int ni = 0; ni < 8; ++ni)
            #pragma unroll
            for (int q = 0; q < 4; ++q) acc[mi][ni][q] = 0.0f;

    // GMEM mappings (per j in 0..3, f = tid + j*256):
    //   A: row = f>>3 (0..127), c4 = f&7  -> W[o0+row][k0 + c4*4 .. +3]
    //   B: k = f>>5 (0..31 over j),  p4 = f&31 -> X[k0+k][p0 + p4*4 .. +3]
    const int a_row = tid >> 3, a_c4 = tid & 7;
    const int b_p4  = tid & 31;

    // prefetch slab 0
    float4 av[4], bv[4];
    #pragma unroll
    for (int j = 0; j < 4; ++j) {
        av[j] = *reinterpret_cast<const float4*>(
            &W[(size_t)(o0 + a_row + j * 32) * CCH + a_c4 * 4]);
        const int bk = (tid + j * 256) >> 5;
        bv[j] = *reinterpret_cast<const float4*>(
            &Xb[(size_t)bk * HWP + p0 + b_p4 * 4]);
    }

    for (int s = 0; s < NSLABS; ++s) {
        if (s > 0) __syncthreads();   // previous compute done before overwrite

        // ---- store A (permuted fragment layout, tf32) ----
        {
            const int ks  = a_c4 >> 1;          // k-step of this float4
            const int jhi = (a_c4 & 1) << 1;    // +2 if cols 4..7 of k8
            #pragma unroll
            for (int j = 0; j < 4; ++j) {
                const int row = a_row + j * 32;
                const int mt  = row >> 4;
                const int jreg = jhi + ((row >> 3) & 1);
                uint32_t* dst = &As[(((mt * 4 + ks) * 33) + (row & 7) * 4) * 4 + jreg];
                dst[0 * 4]  = f2tf32(av[j].x);
                dst[1 * 4]  = f2tf32(av[j].y);
                dst[2 * 4]  = f2tf32(av[j].z);
                dst[3 * 4]  = f2tf32(av[j].w);
            }
        }
        // ---- store B (k x n, pitch 136, tf32) ----
        #pragma unroll
        for (int j = 0; j < 4; ++j) {
            const int bk = (tid + j * 256) >> 5;
            uint4 t;
            t.x = f2tf32(bv[j].x); t.y = f2tf32(bv[j].y);
            t.z = f2tf32(bv[j].z); t.w = f2tf32(bv[j].w);
            *reinterpret_cast<uint4*>(&Bs[bk * BPITCH + b_p4 * 4]) = t;
        }
        __syncthreads();

        // ---- prefetch next slab ----
        if (s + 1 < NSLABS) {
            const int k0n = (s + 1) * TKK;
            #pragma unroll
            for (int j = 0; j < 4; ++j) {
                av[j] = *reinterpret_cast<const float4*>(
                    &W[(size_t)(o0 + a_row + j * 32) * CCH + k0n + a_c4 * 4]);
                const int bk = (tid + j * 256) >> 5;
                bv[j] = *reinterpret_cast<const float4*>(
                    &Xb[(size_t)(k0n + bk) * HWP + p0 + b_p4 * 4]);
            }
        }

        // ---- compute: 4 k-steps x (2 m-tiles x 8 n-tiles) mmas ----
        #pragma unroll
        for (int ks = 0; ks < 4; ++ks) {
            uint32_t a[2][4];
            #pragma unroll
            for (int mi = 0; mi < 2; ++mi) {
                const int mt = wm * 2 + mi;
                const uint4 t = *reinterpret_cast<const uint4*>(
                    &As[((mt * 4 + ks) * 33 + lane) * 4]);
                a[mi][0] = t.x; a[mi][1] = t.y; a[mi][2] = t.z; a[mi][3] = t.w;
            }
            uint32_t b[8][2];
            #pragma unroll
            for (int ni = 0; ni < 8; ++ni) {
                const int col = wn * 64 + ni * 8 + g;
                b[ni][0] = Bs[(ks * 8 + tig) * BPITCH + col];
                b[ni][1] = Bs[(ks * 8 + tig + 4) * BPITCH + col];
            }
            #pragma unroll
            for (int mi = 0; mi < 2; ++mi)
                #pragma unroll
                for (int ni = 0; ni < 8; ++ni)
                    mma16n8k8(acc[mi][ni], a[mi], b[ni]);
        }
    }

    // ---- epilogue: bias + relu -> GMEM ----
    #pragma unroll
    for (int mi = 0; mi < 2; ++mi) {
        const int row_lo = o0 + wm * 32 + mi * 16 + g;
        const int row_hi = row_lo + 8;
        const float blo = __ldg(&bias[row_lo]);
        const float bhi = __ldg(&bias[row_hi]);
        float* plo = &Ob[(size_t)row_lo * HWP + p0 + wn * 64 + tig * 2];
        float* phi = &Ob[(size_t)row_hi * HWP + p0 + wn * 64 + tig * 2];
        #pragma unroll
        for (int ni = 0; ni < 8; ++ni) {
            float2 vlo, vhi;
            vlo.x = fmaxf(acc[mi][ni][0] + blo, 0.0f);
            vlo.y = fmaxf(acc[mi][ni][1] + blo, 0.0f);
            vhi.x = fmaxf(acc[mi][ni][2] + bhi, 0.0f);
            vhi.y = fmaxf(acc[mi][ni][3] + bhi, 0.0f);
            *reinterpret_cast<float2*>(&plo[ni * 8]) = vlo;
            *reinterpret_cast<float2*>(&phi[ni * 8]) = vhi;
        }
    }
}

// ============================================================================
// FFMA2 SGEMM (guarded attention path only: e1/e2)
// ============================================================================
__device__ __forceinline__ unsigned long long pack2(float lo, float hi) {
    unsigned long long r;
    asm("mov.b64 %0, {%1, %2};" : "=l"(r) : "f"(lo), "f"(hi));
    return r;
}
__device__ __forceinline__ void unpack2(unsigned long long v, float& lo, float& hi) {
    asm("mov.b64 {%0, %1}, %2;" : "=f"(lo), "=f"(hi) : "l"(v));
}
__device__ __forceinline__ unsigned long long fma2(unsigned long long a,
                                                   unsigned long long b,
                                                   unsigned long long c) {
    unsigned long long d;
    asm("fma.rn.f32x2 %0, %1, %2, %3;" : "=l"(d) : "l"(a), "l"(b), "l"(c));
    return d;
}

#define BM 128
#define BN 128
#define BK 16
#define APITCH 130

__global__ __launch_bounds__(256, 2)
void gemm_bias_relu(const float* __restrict__ W, const float* __restrict__ X,
                    const float* __restrict__ bias, float* __restrict__ out,
                    int O, int K, int P, const float* __restrict__ guard)
{
    if (guard != nullptr && __ldg(guard) == 0.0f) return;

    const int n  = blockIdx.z;
    const float* Xb = X  + (size_t)n * K * P;
    float*       Ob = out + (size_t)n * O * P;

    __shared__ unsigned long long As[BK * APITCH];
    __shared__ float              Bs[BK * BN];

    const int tid = threadIdx.x;
    const int tx  = tid & 15;
    const int ty  = tid >> 4;
    const int o0  = blockIdx.y * BM;
    const int p0  = blockIdx.x * BN;

    unsigned long long acc[8][4];
    #pragma unroll
    for (int i = 0; i < 8; ++i)
        #pragma unroll
        for (int j = 0; j < 4; ++j) acc[i][j] = 0ULL;

    const int wr0 = tid >> 2;
    const int wc0 = (tid & 3) * 4;
    const int xk0 = tid >> 5;
    const int xc0 = (tid & 31) * 4;

    for (int k0 = 0; k0 < K; k0 += BK) {
        #pragma unroll
        for (int l = 0; l < 2; ++l) {
            const int r = wr0 + l * 64;
            const float4 v = *reinterpret_cast<const float4*>(
                &W[(size_t)(o0 + r) * K + k0 + wc0]);
            As[(wc0 + 0) * APITCH + r] = pack2(v.x, v.x);
            As[(wc0 + 1) * APITCH + r] = pack2(v.y, v.y);
            As[(wc0 + 2) * APITCH + r] = pack2(v.z, v.z);
            As[(wc0 + 3) * APITCH + r] = pack2(v.w, v.w);
        }
        #pragma unroll
        for (int l = 0; l < 2; ++l) {
            const int kk = xk0 + l * 8;
            const float4 v = *reinterpret_cast<const float4*>(
                &Xb[(size_t)(k0 + kk) * P + p0 + xc0]);
            *reinterpret_cast<float4*>(&Bs[kk * BN + xc0]) = v;
        }
        __syncthreads();

        #pragma unroll
        for (int kk = 0; kk < BK; ++kk) {
            unsigned long long a[8];
            const unsigned long long* arow = &As[kk * APITCH + ty * 8];
            #pragma unroll
            for (int i = 0; i < 8; ++i) a[i] = arow[i];
            unsigned long long b[4];
            const unsigned long long* brow =
                reinterpret_cast<const unsigned long long*>(&Bs[kk * BN]) + tx * 4;
            #pragma unroll
            for (int j = 0; j < 4; ++j) b[j] = brow[j];
            #pragma unroll
            for (int i = 0; i < 8; ++i)
                #pragma unroll
                for (int j = 0; j < 4; ++j)
                    acc[i][j] = fma2(a[i], b[j], acc[i][j]);
        }
        __syncthreads();
    }

    #pragma unroll
    for (int i = 0; i < 8; ++i) {
        const int o = o0 + ty * 8 + i;
        const float bvv = __ldg(&bias[o]);
        float* orow = &Ob[(size_t)o * P + p0 + tx * 8];
        #pragma unroll
        for (int j = 0; j < 4; ++j) {
            float lo, hi;
            unpack2(acc[i][j], lo, hi);
            float2 r;
            r.x = fmaxf(lo + bvv, 0.0f);
            r.y = fmaxf(hi + bvv, 0.0f);
            *reinterpret_cast<float2*>(&orow[2 * j]) = r;
        }
    }
}

// ============================================================================
// Attention fallback (guarded): scores + softmax
// ============================================================================
__global__ __launch_bounds__(256)
void attn_softmax_kernel(const float* __restrict__ alpha)
{
    if (__ldg(alpha) == 0.0f) return;

    __shared__ float e1col[DCH];
    __shared__ float red[256];
    const int tid = threadIdx.x;

    for (int row = blockIdx.x; row < NB * HWP; row += gridDim.x) {
        const int n = row >> 12;
        const int i = row & (HWP - 1);
        const float* e1n = g_e1 + (size_t)n * DCH * HWP;
        const float* e2n = g_e2 + (size_t)n * DCH * HWP;
        float* arow = g_attn + (size_t)n * HWP * HWP + (size_t)i * HWP;

        e1col[tid] = e1n[(size_t)tid * HWP + i];
        __syncthreads();

        float sc[16];
        float mx = -3.4e38f;
        #pragma unroll 1
        for (int jj = 0; jj < 16; ++jj) {
            const int j = jj * 256 + tid;
            float s = 0.0f;
            for (int d = 0; d < DCH; ++d) s += e1col[d] * e2n[(size_t)d * HWP + j];
            sc[jj] = s;
            mx = fmaxf(mx, s);
        }
        red[tid] = mx; __syncthreads();
        for (int s = 128; s > 0; s >>= 1) {
            if (tid < s) red[tid] = fmaxf(red[tid], red[tid + s]);
            __syncthreads();
        }
        mx = red[0]; __syncthreads();

        float sum = 0.0f;
        #pragma unroll
        for (int jj = 0; jj < 16; ++jj) { sc[jj] = expf(sc[jj] - mx); sum += sc[jj]; }
        red[tid] = sum; __syncthreads();
        for (int s = 128; s > 0; s >>= 1) {
            if (tid < s) red[tid] += red[tid + s];
            __syncthreads();
        }
        const float inv = 1.0f / red[0];
        __syncthreads();

        #pragma unroll
        for (int jj = 0; jj < 16; ++jj) arow[jj * 256 + tid] = sc[jj] * inv;
        __syncthreads();
    }
}

// ============================================================================
// Attention fallback bmm (guarded)
// ============================================================================
__global__ __launch_bounds__(256)
void bmm_alpha_kernel(const float* __restrict__ x, float* __restrict__ out,
                      const float* __restrict__ alpha_p)
{
    const float alpha = __ldg(alpha_p);
    if (alpha == 0.0f) return;

    __shared__ float xs[HWP];
    const int tid = threadIdx.x;

    for (int row = blockIdx.x; row < NB * CCH; row += gridDim.x) {
        const int n = row >> 11;
        const int c = row & (CCH - 1);
        const float* xr = x + ((size_t)n * CCH + c) * HWP;
        const float* an = g_attn + (size_t)n * HWP * HWP;
        float* orow = out + ((size_t)n * CCH + c) * HWP;

        for (int j = tid; j < HWP; j += 256) xs[j] = xr[j];
        __syncthreads();

        for (int i = tid; i < HWP; i += 256) {
            float acc = 0.0f;
            const float* ai = an + (size_t)i * HWP;
            for (int j = 0; j < HWP; ++j) acc += xs[j] * ai[j];
            orow[i] += alpha * acc;
        }
        __syncthreads();
    }
}

// ============================================================================
// launch
// ============================================================================
extern "C" void kernel_launch(void* const* d_in, const int* in_sizes, int n_in,
                              void* d_out, int out_size)
{
    const float* x     = (const float*)d_in[0];
    const float* w1    = (const float*)d_in[1];
    const float* b1    = (const float*)d_in[2];
    const float* w2    = (const float*)d_in[3];
    const float* b2    = (const float*)d_in[4];
    const float* w3    = (const float*)d_in[5];
    const float* b3    = (const float*)d_in[6];
    const float* alpha = (const float*)d_in[7];
    float* out = (float*)d_out;

    float *e1p = nullptr, *e2p = nullptr;
    cudaGetSymbolAddress((void**)&e1p, g_e1);
    cudaGetSymbolAddress((void**)&e2p, g_e2);

    // assembly = relu(w3 @ x + b3) -> d_out  (tensor cores, tf32 mma.sync)
    gemm_mma_bias_relu<<<dim3(HWP / TN, CCH / TM, NB), 256>>>(w3, x, b3, out);

    // --- attention path: all guarded, early-exit when alpha == 0 ---
    gemm_bias_relu<<<dim3(HWP / BN, DCH / BM, NB), 256>>>(
        w1, x, b1, e1p, DCH, CCH, HWP, alpha);
    gemm_bias_relu<<<dim3(HWP / BN, DCH / BM, NB), 256>>>(
        w2, x, b2, e2p, DCH, CCH, HWP, alpha);
    attn_softmax_kernel<<<2048, 256>>>(alpha);
    bmm_alpha_kernel<<<1024, 256>>>(x, out, alpha);
}

// round 4
// speedup vs baseline: 3.8427x; 1.0934x over previous
#include <cuda_runtime.h>
#include <cuda_bf16.h>
#include <cstdint>

// ============================================================================
// NonLocalPositionAttention
//   y = alpha * (x @ softmax(e1^T e2)^T) + relu(w3 @ x + b3)
// alpha == 0 for benchmark inputs -> y == relu(w3 @ x + b3).
// Assembly GEMM: mma.sync tf32 tensor cores, cp.async 3-stage pipeline over
// pre-rounded (tf32 RNA) operands. Attention branch implemented but guarded.
// ============================================================================

#define NB   4
#define CCH  2048
#define DCH  256
#define HWP  4096

// ---- scratch ---------------------------------------------------------------
__device__ float g_e1[(size_t)NB * DCH * HWP];
__device__ float g_e2[(size_t)NB * DCH * HWP];
__device__ float g_attn[(size_t)NB * HWP * HWP];
__device__ float g_w3r[(size_t)CCH * CCH];          // tf32-rounded W3
__device__ float g_xr[(size_t)NB * CCH * HWP];      // tf32-rounded X

// ============================================================================
// helpers
// ============================================================================
__device__ __forceinline__ uint32_t f2tf32(float x) {
    uint32_t u;
    asm("cvt.rna.tf32.f32 %0, %1;" : "=r"(u) : "f"(x));
    return u;
}
__device__ __forceinline__ uint32_t smem_u32(const void* p) {
    uint32_t a;
    asm("{ .reg .u64 t; cvta.to.shared.u64 t, %1; cvt.u32.u64 %0, t; }"
        : "=r"(a) : "l"(p));
    return a;
}
__device__ __forceinline__ void cp_async16(uint32_t dst, const void* src) {
    asm volatile("cp.async.cg.shared.global [%0], [%1], 16;"
                 :: "r"(dst), "l"(src) : "memory");
}
#define CP_COMMIT() asm volatile("cp.async.commit_group;" ::: "memory")
#define CP_WAIT1()  asm volatile("cp.async.wait_group 1;" ::: "memory")

__device__ __forceinline__ void mma16n8k8(float* d, const uint32_t* a,
                                          const uint32_t* b) {
    asm volatile(
        "mma.sync.aligned.m16n8k8.row.col.f32.tf32.tf32.f32 "
        "{%0,%1,%2,%3}, {%4,%5,%6,%7}, {%8,%9}, {%0,%1,%2,%3};"
        : "+f"(d[0]), "+f"(d[1]), "+f"(d[2]), "+f"(d[3])
        : "r"(a[0]), "r"(a[1]), "r"(a[2]), "r"(a[3]), "r"(b[0]), "r"(b[1]));
}

// ============================================================================
// pre-pass: round fp32 -> tf32(RNA) stored as fp32 bits
// ============================================================================
__global__ void __launch_bounds__(256)
round_tf32_kernel(const float4* __restrict__ src, uint4* __restrict__ dst,
                  int n4)
{
    for (int i = blockIdx.x * blockDim.x + threadIdx.x; i < n4;
         i += gridDim.x * blockDim.x) {
        const float4 v = src[i];
        uint4 t;
        t.x = f2tf32(v.x); t.y = f2tf32(v.y);
        t.z = f2tf32(v.z); t.w = f2tf32(v.w);
        dst[i] = t;
    }
}

// ============================================================================
// Tensor-core tf32 GEMM + bias + relu (inputs pre-rounded):
//   out[n,o,p] = relu( sum_c W[o,c] * X[n,c,p] + bias[o] )
// CTA tile 256(m) x 128(n) x 32(k); 512 threads = 16 warps as 4(m) x 4(n);
// warp tile 64x32. cp.async cg, 3-stage ring, depth-2 prefetch, 1 sync/slab.
// A smem pitch 36 floats, B pitch 136 floats -> conflict-free frag LDS.32.
// ============================================================================
#define GTM 256
#define GTN 128
#define GTK 32
#define G_NSLABS (CCH / GTK)                 // 64
#define APITCH 36                            // floats
#define BPITCH 136                           // floats
#define A_STAGE (GTM * APITCH * 4)           // 36864 B
#define B_STAGE (GTK * BPITCH * 4)           // 17408 B
#define STAGE_B (A_STAGE + B_STAGE)          // 54272 B
#define GEMM_DSMEM (3 * STAGE_B)             // 162816 B

__global__ void __launch_bounds__(512, 1)
gemm_mma_bias_relu(const float* __restrict__ Wr, const float* __restrict__ Xr,
                   const float* __restrict__ bias, float* __restrict__ out)
{
    extern __shared__ char smem[];
    const uint32_t smem_base = smem_u32(smem);

    const int tid  = threadIdx.x;
    const int wid  = tid >> 5;
    const int lane = tid & 31;
    const int g    = lane >> 2;
    const int tig  = lane & 3;
    const int wm   = wid >> 2;     // 0..3
    const int wn   = wid & 3;      // 0..3

    const int n  = blockIdx.z;
    const int o0 = blockIdx.y * GTM;
    const int p0 = blockIdx.x * GTN;
    const float* Xb = Xr + (size_t)n * CCH * HWP;
    float*       Ob = out + (size_t)n * CCH * HWP;

    float acc[4][4][4];
    #pragma unroll
    for (int mi = 0; mi < 4; ++mi)
        #pragma unroll
        for (int ni = 0; ni < 4; ++ni)
            #pragma unroll
            for (int q = 0; q < 4; ++q) acc[mi][ni][q] = 0.0f;

    // copy mappings
    //   A: 2048 16B-chunks: c = tid + j*512, j<4: row=c>>3 (0..255), cq=c&7
    //   B: 1024 16B-chunks: c = tid + j*512, j<2: k=c>>5 (0..31), nq=c&31
    const int a_row = tid >> 3, a_cq = tid & 7;
    const int b_nq  = tid & 31;

    #define ISSUE_SLAB(S, BUF) do {                                          \
        const int _k0 = (S) * GTK;                                           \
        const uint32_t _dA = smem_base + (BUF) * STAGE_B;                    \
        const uint32_t _dB = _dA + A_STAGE;                                  \
        _Pragma("unroll")                                                    \
        for (int j = 0; j < 4; ++j) {                                        \
            const int row = a_row + j * 64;                                  \
            cp_async16(_dA + row * (APITCH * 4) + a_cq * 16,                 \
                       &Wr[(size_t)(o0 + row) * CCH + _k0 + a_cq * 4]);      \
        }                                                                    \
        _Pragma("unroll")                                                    \
        for (int j = 0; j < 2; ++j) {                                        \
            const int k = (tid + j * 512) >> 5;                              \
            cp_async16(_dB + k * (BPITCH * 4) + b_nq * 16,                   \
                       &Xb[(size_t)(_k0 + k) * HWP + p0 + b_nq * 4]);        \
        }                                                                    \
    } while (0)

    // prologue: slabs 0 and 1 in flight
    ISSUE_SLAB(0, 0); CP_COMMIT();
    ISSUE_SLAB(1, 1); CP_COMMIT();

    for (int s = 0; s < G_NSLABS; ++s) {
        CP_WAIT1();          // my slab-s copies complete (slab s+1 may pend)
        __syncthreads();     // publish all threads' slab-s data; all warps
                             // done reading buffer (s+2)%3 (== slab s-1)
        if (s + 2 < G_NSLABS) ISSUE_SLAB(s + 2, (s + 2) % 3);
        CP_COMMIT();

        const uint32_t* As = reinterpret_cast<const uint32_t*>(
            smem + (s % 3) * STAGE_B);
        const uint32_t* Bs = As + GTM * APITCH;

        #pragma unroll
        for (int ks = 0; ks < 4; ++ks) {
            uint32_t a[4][4];
            #pragma unroll
            for (int mi = 0; mi < 4; ++mi) {
                const int m = wm * 64 + mi * 16;
                const int k = ks * 8 + tig;
                a[mi][0] = As[(m + g) * APITCH + k];
                a[mi][1] = As[(m + 8 + g) * APITCH + k];
                a[mi][2] = As[(m + g) * APITCH + k + 4];
                a[mi][3] = As[(m + 8 + g) * APITCH + k + 4];
            }
            uint32_t b[4][2];
            #pragma unroll
            for (int ni = 0; ni < 4; ++ni) {
                const int col = wn * 32 + ni * 8 + g;
                b[ni][0] = Bs[(ks * 8 + tig) * BPITCH + col];
                b[ni][1] = Bs[(ks * 8 + tig + 4) * BPITCH + col];
            }
            #pragma unroll
            for (int mi = 0; mi < 4; ++mi)
                #pragma unroll
                for (int ni = 0; ni < 4; ++ni)
                    mma16n8k8(acc[mi][ni], a[mi], b[ni]);
        }
    }

    // ---- epilogue: bias + relu -> GMEM ----
    #pragma unroll
    for (int mi = 0; mi < 4; ++mi) {
        const int row_lo = o0 + wm * 64 + mi * 16 + g;
        const int row_hi = row_lo + 8;
        const float blo = __ldg(&bias[row_lo]);
        const float bhi = __ldg(&bias[row_hi]);
        float* plo = &Ob[(size_t)row_lo * HWP + p0 + wn * 32 + tig * 2];
        float* phi = &Ob[(size_t)row_hi * HWP + p0 + wn * 32 + tig * 2];
        #pragma unroll
        for (int ni = 0; ni < 4; ++ni) {
            float2 vlo, vhi;
            vlo.x = fmaxf(acc[mi][ni][0] + blo, 0.0f);
            vlo.y = fmaxf(acc[mi][ni][1] + blo, 0.0f);
            vhi.x = fmaxf(acc[mi][ni][2] + bhi, 0.0f);
            vhi.y = fmaxf(acc[mi][ni][3] + bhi, 0.0f);
            *reinterpret_cast<float2*>(&plo[ni * 8]) = vlo;
            *reinterpret_cast<float2*>(&phi[ni * 8]) = vhi;
        }
    }
}

// ============================================================================
// FFMA2 SGEMM (guarded attention path only: e1/e2)
// ============================================================================
__device__ __forceinline__ unsigned long long pack2(float lo, float hi) {
    unsigned long long r;
    asm("mov.b64 %0, {%1, %2};" : "=l"(r) : "f"(lo), "f"(hi));
    return r;
}
__device__ __forceinline__ void unpack2(unsigned long long v, float& lo, float& hi) {
    asm("mov.b64 {%0, %1}, %2;" : "=f"(lo), "=f"(hi) : "l"(v));
}
__device__ __forceinline__ unsigned long long fma2(unsigned long long a,
                                                   unsigned long long b,
                                                   unsigned long long c) {
    unsigned long long d;
    asm("fma.rn.f32x2 %0, %1, %2, %3;" : "=l"(d) : "l"(a), "l"(b), "l"(c));
    return d;
}

#define BM 128
#define BN 128
#define BK 16
#define FPITCH 130

__global__ __launch_bounds__(256, 2)
void gemm_bias_relu(const float* __restrict__ W, const float* __restrict__ X,
                    const float* __restrict__ bias, float* __restrict__ out,
                    int O, int K, int P, const float* __restrict__ guard)
{
    if (guard != nullptr && __ldg(guard) == 0.0f) return;

    const int n  = blockIdx.z;
    const float* Xb = X  + (size_t)n * K * P;
    float*       Ob = out + (size_t)n * O * P;

    __shared__ unsigned long long As[BK * FPITCH];
    __shared__ float              Bs[BK * BN];

    const int tid = threadIdx.x;
    const int tx  = tid & 15;
    const int ty  = tid >> 4;
    const int o0  = blockIdx.y * BM;
    const int p0  = blockIdx.x * BN;

    unsigned long long acc[8][4];
    #pragma unroll
    for (int i = 0; i < 8; ++i)
        #pragma unroll
        for (int j = 0; j < 4; ++j) acc[i][j] = 0ULL;

    const int wr0 = tid >> 2;
    const int wc0 = (tid & 3) * 4;
    const int xk0 = tid >> 5;
    const int xc0 = (tid & 31) * 4;

    for (int k0 = 0; k0 < K; k0 += BK) {
        #pragma unroll
        for (int l = 0; l < 2; ++l) {
            const int r = wr0 + l * 64;
            const float4 v = *reinterpret_cast<const float4*>(
                &W[(size_t)(o0 + r) * K + k0 + wc0]);
            As[(wc0 + 0) * FPITCH + r] = pack2(v.x, v.x);
            As[(wc0 + 1) * FPITCH + r] = pack2(v.y, v.y);
            As[(wc0 + 2) * FPITCH + r] = pack2(v.z, v.z);
            As[(wc0 + 3) * FPITCH + r] = pack2(v.w, v.w);
        }
        #pragma unroll
        for (int l = 0; l < 2; ++l) {
            const int kk = xk0 + l * 8;
            const float4 v = *reinterpret_cast<const float4*>(
                &Xb[(size_t)(k0 + kk) * P + p0 + xc0]);
            *reinterpret_cast<float4*>(&Bs[kk * BN + xc0]) = v;
        }
        __syncthreads();

        #pragma unroll
        for (int kk = 0; kk < BK; ++kk) {
            unsigned long long a[8];
            const unsigned long long* arow = &As[kk * FPITCH + ty * 8];
            #pragma unroll
            for (int i = 0; i < 8; ++i) a[i] = arow[i];
            unsigned long long b[4];
            const unsigned long long* brow =
                reinterpret_cast<const unsigned long long*>(&Bs[kk * BN]) + tx * 4;
            #pragma unroll
            for (int j = 0; j < 4; ++j) b[j] = brow[j];
            #pragma unroll
            for (int i = 0; i < 8; ++i)
                #pragma unroll
                for (int j = 0; j < 4; ++j)
                    acc[i][j] = fma2(a[i], b[j], acc[i][j]);
        }
        __syncthreads();
    }

    #pragma unroll
    for (int i = 0; i < 8; ++i) {
        const int o = o0 + ty * 8 + i;
        const float bvv = __ldg(&bias[o]);
        float* orow = &Ob[(size_t)o * P + p0 + tx * 8];
        #pragma unroll
        for (int j = 0; j < 4; ++j) {
            float lo, hi;
            unpack2(acc[i][j], lo, hi);
            float2 r;
            r.x = fmaxf(lo + bvv, 0.0f);
            r.y = fmaxf(hi + bvv, 0.0f);
            *reinterpret_cast<float2*>(&orow[2 * j]) = r;
        }
    }
}

// ============================================================================
// Attention fallback (guarded): scores + softmax
// ============================================================================
__global__ __launch_bounds__(256)
void attn_softmax_kernel(const float* __restrict__ alpha)
{
    if (__ldg(alpha) == 0.0f) return;

    __shared__ float e1col[DCH];
    __shared__ float red[256];
    const int tid = threadIdx.x;

    for (int row = blockIdx.x; row < NB * HWP; row += gridDim.x) {
        const int n = row >> 12;
        const int i = row & (HWP - 1);
        const float* e1n = g_e1 + (size_t)n * DCH * HWP;
        const float* e2n = g_e2 + (size_t)n * DCH * HWP;
        float* arow = g_attn + (size_t)n * HWP * HWP + (size_t)i * HWP;

        e1col[tid] = e1n[(size_t)tid * HWP + i];
        __syncthreads();

        float sc[16];
        float mx = -3.4e38f;
        #pragma unroll 1
        for (int jj = 0; jj < 16; ++jj) {
            const int j = jj * 256 + tid;
            float s = 0.0f;
            for (int d = 0; d < DCH; ++d) s += e1col[d] * e2n[(size_t)d * HWP + j];
            sc[jj] = s;
            mx = fmaxf(mx, s);
        }
        red[tid] = mx; __syncthreads();
        for (int s = 128; s > 0; s >>= 1) {
            if (tid < s) red[tid] = fmaxf(red[tid], red[tid + s]);
            __syncthreads();
        }
        mx = red[0]; __syncthreads();

        float sum = 0.0f;
        #pragma unroll
        for (int jj = 0; jj < 16; ++jj) { sc[jj] = expf(sc[jj] - mx); sum += sc[jj]; }
        red[tid] = sum; __syncthreads();
        for (int s = 128; s > 0; s >>= 1) {
            if (tid < s) red[tid] += red[tid + s];
            __syncthreads();
        }
        const float inv = 1.0f / red[0];
        __syncthreads();

        #pragma unroll
        for (int jj = 0; jj < 16; ++jj) arow[jj * 256 + tid] = sc[jj] * inv;
        __syncthreads();
    }
}

// ============================================================================
// Attention fallback bmm (guarded)
// ============================================================================
__global__ __launch_bounds__(256)
void bmm_alpha_kernel(const float* __restrict__ x, float* __restrict__ out,
                      const float* __restrict__ alpha_p)
{
    const float alpha = __ldg(alpha_p);
    if (alpha == 0.0f) return;

    __shared__ float xs[HWP];
    const int tid = threadIdx.x;

    for (int row = blockIdx.x; row < NB * CCH; row += gridDim.x) {
        const int n = row >> 11;
        const int c = row & (CCH - 1);
        const float* xr = x + ((size_t)n * CCH + c) * HWP;
        const float* an = g_attn + (size_t)n * HWP * HWP;
        float* orow = out + ((size_t)n * CCH + c) * HWP;

        for (int j = tid; j < HWP; j += 256) xs[j] = xr[j];
        __syncthreads();

        for (int i = tid; i < HWP; i += 256) {
            float acc = 0.0f;
            const float* ai = an + (size_t)i * HWP;
            for (int j = 0; j < HWP; ++j) acc += xs[j] * ai[j];
            orow[i] += alpha * acc;
        }
        __syncthreads();
    }
}

// ============================================================================
// launch
// ============================================================================
extern "C" void kernel_launch(void* const* d_in, const int* in_sizes, int n_in,
                              void* d_out, int out_size)
{
    const float* x     = (const float*)d_in[0];
    const float* w1    = (const float*)d_in[1];
    const float* b1    = (const float*)d_in[2];
    const float* w2    = (const float*)d_in[3];
    const float* b2    = (const float*)d_in[4];
    const float* w3    = (const float*)d_in[5];
    const float* b3    = (const float*)d_in[6];
    const float* alpha = (const float*)d_in[7];
    float* out = (float*)d_out;

    float *e1p = nullptr, *e2p = nullptr, *w3r = nullptr, *xr = nullptr;
    cudaGetSymbolAddress((void**)&e1p, g_e1);
    cudaGetSymbolAddress((void**)&e2p, g_e2);
    cudaGetSymbolAddress((void**)&w3r, g_w3r);
    cudaGetSymbolAddress((void**)&xr,  g_xr);

    static bool attr_done = false;
    if (!attr_done) {
        cudaFuncSetAttribute(gemm_mma_bias_relu,
                             cudaFuncAttributeMaxDynamicSharedMemorySize,
                             GEMM_DSMEM);
        attr_done = true;
    }

    // pre-pass: tf32-round W3 and X
    round_tf32_kernel<<<2048, 256>>>((const float4*)w3, (uint4*)w3r,
                                     CCH * CCH / 4);
    round_tf32_kernel<<<8192, 256>>>((const float4*)x, (uint4*)xr,
                                     NB * CCH * HWP / 4);

    // assembly = relu(w3 @ x + b3) -> d_out
    gemm_mma_bias_relu<<<dim3(HWP / GTN, CCH / GTM, NB), 512, GEMM_DSMEM>>>(
        w3r, xr, b3, out);

    // --- attention path: all guarded, early-exit when alpha == 0 ---
    gemm_bias_relu<<<dim3(HWP / BN, DCH / BM, NB), 256>>>(
        w1, x, b1, e1p, DCH, CCH, HWP, alpha);
    gemm_bias_relu<<<dim3(HWP / BN, DCH / BM, NB), 256>>>(
        w2, x, b2, e2p, DCH, CCH, HWP, alpha);
    attn_softmax_kernel<<<2048, 256>>>(alpha);
    bmm_alpha_kernel<<<1024, 256>>>(x, out, alpha);
}

// round 7
// speedup vs baseline: 4.1467x; 1.0791x over previous
#include <cuda_runtime.h>
#include <cuda_bf16.h>
#include <cuda_fp16.h>
#include <cstdint>

// ============================================================================
// NonLocalPositionAttention
//   y = alpha * (x @ softmax(e1^T e2)^T) + relu(w3 @ x + b3)
// alpha == 0 for benchmark inputs -> y == relu(w3 @ x + b3).
// Assembly GEMM: mma.sync m16n8k16 fp16 (same significand as tf32, 2x K/instr)
// over pre-converted operands (W3 -> fp16 [o][k]; X -> fp16 transposed
// [n][p][k]). cp.async 3-stage pipeline. Attention branch guarded.
// R6 fix: transpose kernel store phase covered only half the c-range
// (cp=tid&15); now full 32x32 half2 coverage per tile.
// ============================================================================

#define NB   4
#define CCH  2048
#define DCH  256
#define HWP  4096

// ---- scratch ---------------------------------------------------------------
__device__ float  g_e1[(size_t)NB * DCH * HWP];
__device__ float  g_e2[(size_t)NB * DCH * HWP];
__device__ float  g_attn[(size_t)NB * HWP * HWP];
__device__ __half g_w3h[(size_t)CCH * CCH];           // fp16 W3 [o][k]
__device__ __half g_xth[(size_t)NB * HWP * CCH];      // fp16 X^T [n][p][k]

// ============================================================================
// helpers
// ============================================================================
__device__ __forceinline__ uint32_t smem_u32(const void* p) {
    uint32_t a;
    asm("{ .reg .u64 t; cvta.to.shared.u64 t, %1; cvt.u32.u64 %0, t; }"
        : "=r"(a) : "l"(p));
    return a;
}
__device__ __forceinline__ void cp_async16(uint32_t dst, const void* src) {
    asm volatile("cp.async.cg.shared.global [%0], [%1], 16;"
                 :: "r"(dst), "l"(src) : "memory");
}
#define CP_COMMIT() asm volatile("cp.async.commit_group;" ::: "memory")
#define CP_WAIT1()  asm volatile("cp.async.wait_group 1;" ::: "memory")

__device__ __forceinline__ void mma_f16(float* d, const uint32_t* a,
                                        const uint32_t* b) {
    asm volatile(
        "mma.sync.aligned.m16n8k16.row.col.f32.f16.f16.f32 "
        "{%0,%1,%2,%3}, {%4,%5,%6,%7}, {%8,%9}, {%0,%1,%2,%3};"
        : "+f"(d[0]), "+f"(d[1]), "+f"(d[2]), "+f"(d[3])
        : "r"(a[0]), "r"(a[1]), "r"(a[2]), "r"(a[3]), "r"(b[0]), "r"(b[1]));
}

// ============================================================================
// pre-pass 1: X [n][c][p] fp32 -> X^T [n][p][c] fp16  (tiled transpose)
// tile: 64 c x 32 p
// ============================================================================
__global__ void __launch_bounds__(256)
xpose_half_kernel(const float* __restrict__ x, __half* __restrict__ xt)
{
    __shared__ float t[32][65];   // [p_local][c_local]
    const int n  = blockIdx.z;
    const int c0 = blockIdx.y * 64;
    const int p0 = blockIdx.x * 32;
    const int tid = threadIdx.x;

    const float* xb = x + (size_t)n * CCH * HWP;
    __half* xtb = xt + (size_t)n * HWP * CCH;

    {
        const int p_l = tid & 31;
        #pragma unroll
        for (int i = 0; i < 8; ++i) {
            const int c_l = (tid >> 5) + i * 8;
            t[p_l][c_l] = xb[(size_t)(c0 + c_l) * HWP + p0 + p_l];
        }
    }
    __syncthreads();
    {
        const int cp = tid & 31;            // half2 pair index (c), 0..31
        #pragma unroll
        for (int i = 0; i < 4; ++i) {
            const int p_l = (tid >> 5) + i * 8;   // 0..31
            __half2 v = __floats2half2_rn(t[p_l][2 * cp], t[p_l][2 * cp + 1]);
            *reinterpret_cast<__half2*>(
                &xtb[(size_t)(p0 + p_l) * CCH + c0 + 2 * cp]) = v;
        }
    }
}

// ============================================================================
// pre-pass 2: W3 fp32 -> fp16 (layout preserved)
// ============================================================================
__global__ void __launch_bounds__(256)
cvt_half_kernel(const float4* __restrict__ src, uint2* __restrict__ dst, int n4)
{
    for (int i = blockIdx.x * blockDim.x + threadIdx.x; i < n4;
         i += gridDim.x * blockDim.x) {
        const float4 v = src[i];
        __half2 lo = __floats2half2_rn(v.x, v.y);
        __half2 hi = __floats2half2_rn(v.z, v.w);
        uint2 o;
        o.x = *reinterpret_cast<uint32_t*>(&lo);
        o.y = *reinterpret_cast<uint32_t*>(&hi);
        dst[i] = o;
    }
}

// ============================================================================
// fp16 tensor-core GEMM + bias + relu:
//   out[n,o,p] = relu( sum_c W[o,c] * X[n,c,p] + bias[o] )
// CTA tile 128(m) x 256(n) x 32(k); 256 threads = 8 warps (2m x 4n);
// warp tile 64x64. A/B smem rows pitch 20 words (32 fp16 + pad) ->
// conflict-free fragment loads (banks {20g mod 32} + tig cover 0..31).
// cp.async cg 3-stage ring, 1 syncthreads per slab.
// ============================================================================
#define HTM 128
#define HTN 256
#define HTK 32
#define H_NSLABS (CCH / HTK)                 // 64
#define HPITCH_B 80                          // bytes per smem row (32 fp16 + pad)
#define A_STAGE (HTM * HPITCH_B)             // 10240
#define B_STAGE (HTN * HPITCH_B)             // 20480
#define STAGE_B (A_STAGE + B_STAGE)          // 30720
#define GEMM_DSMEM (3 * STAGE_B)             // 92160

__global__ void __launch_bounds__(256, 1)
gemm_f16_bias_relu(const __half* __restrict__ Wh, const __half* __restrict__ Xth,
                   const float* __restrict__ bias, float* __restrict__ out)
{
    extern __shared__ char smem[];
    const uint32_t smem_base = smem_u32(smem);

    const int tid  = threadIdx.x;
    const int wid  = tid >> 5;
    const int lane = tid & 31;
    const int g    = lane >> 2;
    const int tig  = lane & 3;
    const int wm   = wid >> 2;     // 0..1
    const int wn   = wid & 3;      // 0..3

    const int n  = blockIdx.z;
    const int o0 = blockIdx.y * HTM;
    const int p0 = blockIdx.x * HTN;
    const __half* Xb = Xth + (size_t)n * HWP * CCH;
    float*        Ob = out + (size_t)n * CCH * HWP;

    float acc[4][8][4];
    #pragma unroll
    for (int mi = 0; mi < 4; ++mi)
        #pragma unroll
        for (int ni = 0; ni < 8; ++ni)
            #pragma unroll
            for (int q = 0; q < 4; ++q) acc[mi][ni][q] = 0.0f;

    // cp.async mappings (16B chunks of 8 fp16):
    //   A: 512 chunks: c = tid + j*256 (j<2): row=c>>2 (0..127), cw=c&3
    //   B: 1024 chunks: c = tid + j*256 (j<4): row=c>>2 (0..255), cw=c&3
    const int cp_row = tid >> 2, cp_cw = tid & 3;

    #define ISSUE_SLAB(S, BUF) do {                                           \
        const int _k0 = (S) * HTK;                                            \
        const uint32_t _dA = smem_base + (BUF) * STAGE_B;                     \
        const uint32_t _dB = _dA + A_STAGE;                                   \
        _Pragma("unroll")                                                     \
        for (int j = 0; j < 2; ++j) {                                         \
            const int row = cp_row + j * 64;                                  \
            cp_async16(_dA + row * HPITCH_B + cp_cw * 16,                     \
                       &Wh[(size_t)(o0 + row) * CCH + _k0 + cp_cw * 8]);      \
        }                                                                     \
        _Pragma("unroll")                                                     \
        for (int j = 0; j < 4; ++j) {                                         \
            const int row = cp_row + j * 64;                                  \
            cp_async16(_dB + row * HPITCH_B + cp_cw * 16,                     \
                       &Xb[(size_t)(p0 + row) * CCH + _k0 + cp_cw * 8]);      \
        }                                                                     \
    } while (0)

    ISSUE_SLAB(0, 0); CP_COMMIT();
    ISSUE_SLAB(1, 1); CP_COMMIT();

    for (int s = 0; s < H_NSLABS; ++s) {
        CP_WAIT1();
        __syncthreads();
        if (s + 2 < H_NSLABS) ISSUE_SLAB(s + 2, (s + 2) % 3);
        CP_COMMIT();

        const uint32_t* As = reinterpret_cast<const uint32_t*>(
            smem + (s % 3) * STAGE_B);
        const uint32_t* Bs = reinterpret_cast<const uint32_t*>(
            smem + (s % 3) * STAGE_B + A_STAGE);

        #pragma unroll
        for (int ks = 0; ks < 2; ++ks) {
            const int kw = ks * 8 + tig;      // word index within 20-word row
            uint32_t a[4][4];
            #pragma unroll
            for (int mi = 0; mi < 4; ++mi) {
                const int m = wm * 64 + mi * 16;
                a[mi][0] = As[(m + g) * 20 + kw];
                a[mi][1] = As[(m + 8 + g) * 20 + kw];
                a[mi][2] = As[(m + g) * 20 + kw + 4];
                a[mi][3] = As[(m + 8 + g) * 20 + kw + 4];
            }
            uint32_t b[8][2];
            #pragma unroll
            for (int ni = 0; ni < 8; ++ni) {
                const int col = wn * 64 + ni * 8 + g;
                b[ni][0] = Bs[col * 20 + kw];
                b[ni][1] = Bs[col * 20 + kw + 4];
            }
            #pragma unroll
            for (int mi = 0; mi < 4; ++mi)
                #pragma unroll
                for (int ni = 0; ni < 8; ++ni)
                    mma_f16(acc[mi][ni], a[mi], b[ni]);
        }
    }

    // ---- epilogue: bias + relu -> GMEM ----
    #pragma unroll
    for (int mi = 0; mi < 4; ++mi) {
        const int row_lo = o0 + wm * 64 + mi * 16 + g;
        const int row_hi = row_lo + 8;
        const float blo = __ldg(&bias[row_lo]);
        const float bhi = __ldg(&bias[row_hi]);
        float* plo = &Ob[(size_t)row_lo * HWP + p0 + wn * 64 + tig * 2];
        float* phi = &Ob[(size_t)row_hi * HWP + p0 + wn * 64 + tig * 2];
        #pragma unroll
        for (int ni = 0; ni < 8; ++ni) {
            float2 vlo, vhi;
            vlo.x = fmaxf(acc[mi][ni][0] + blo, 0.0f);
            vlo.y = fmaxf(acc[mi][ni][1] + blo, 0.0f);
            vhi.x = fmaxf(acc[mi][ni][2] + bhi, 0.0f);
            vhi.y = fmaxf(acc[mi][ni][3] + bhi, 0.0f);
            *reinterpret_cast<float2*>(&plo[ni * 8]) = vlo;
            *reinterpret_cast<float2*>(&phi[ni * 8]) = vhi;
        }
    }
}

// ============================================================================
// FFMA2 SGEMM (guarded attention path only: e1/e2)
// ============================================================================
__device__ __forceinline__ unsigned long long pack2(float lo, float hi) {
    unsigned long long r;
    asm("mov.b64 %0, {%1, %2};" : "=l"(r) : "f"(lo), "f"(hi));
    return r;
}
__device__ __forceinline__ void unpack2(unsigned long long v, float& lo, float& hi) {
    asm("mov.b64 {%0, %1}, %2;" : "=f"(lo), "=f"(hi) : "l"(v));
}
__device__ __forceinline__ unsigned long long fma2(unsigned long long a,
                                                   unsigned long long b,
                                                   unsigned long long c) {
    unsigned long long d;
    asm("fma.rn.f32x2 %0, %1, %2, %3;" : "=l"(d) : "l"(a), "l"(b), "l"(c));
    return d;
}

#define BM 128
#define BN 128
#define BK 16
#define FPITCH 130

__global__ __launch_bounds__(256, 2)
void gemm_bias_relu(const float* __restrict__ W, const float* __restrict__ X,
                    const float* __restrict__ bias, float* __restrict__ out,
                    int O, int K, int P, const float* __restrict__ guard)
{
    if (guard != nullptr && __ldg(guard) == 0.0f) return;

    const int n  = blockIdx.z;
    const float* Xb = X  + (size_t)n * K * P;
    float*       Ob = out + (size_t)n * O * P;

    __shared__ unsigned long long As[BK * FPITCH];
    __shared__ float              Bs[BK * BN];

    const int tid = threadIdx.x;
    const int tx  = tid & 15;
    const int ty  = tid >> 4;
    const int o0  = blockIdx.y * BM;
    const int p0  = blockIdx.x * BN;

    unsigned long long acc[8][4];
    #pragma unroll
    for (int i = 0; i < 8; ++i)
        #pragma unroll
        for (int j = 0; j < 4; ++j) acc[i][j] = 0ULL;

    const int wr0 = tid >> 2;
    const int wc0 = (tid & 3) * 4;
    const int xk0 = tid >> 5;
    const int xc0 = (tid & 31) * 4;

    for (int k0 = 0; k0 < K; k0 += BK) {
        #pragma unroll
        for (int l = 0; l < 2; ++l) {
            const int r = wr0 + l * 64;
            const float4 v = *reinterpret_cast<const float4*>(
                &W[(size_t)(o0 + r) * K + k0 + wc0]);
            As[(wc0 + 0) * FPITCH + r] = pack2(v.x, v.x);
            As[(wc0 + 1) * FPITCH + r] = pack2(v.y, v.y);
            As[(wc0 + 2) * FPITCH + r] = pack2(v.z, v.z);
            As[(wc0 + 3) * FPITCH + r] = pack2(v.w, v.w);
        }
        #pragma unroll
        for (int l = 0; l < 2; ++l) {
            const int kk = xk0 + l * 8;
            const float4 v = *reinterpret_cast<const float4*>(
                &Xb[(size_t)(k0 + kk) * P + p0 + xc0]);
            *reinterpret_cast<float4*>(&Bs[kk * BN + xc0]) = v;
        }
        __syncthreads();

        #pragma unroll
        for (int kk = 0; kk < BK; ++kk) {
            unsigned long long a[8];
            const unsigned long long* arow = &As[kk * FPITCH + ty * 8];
            #pragma unroll
            for (int i = 0; i < 8; ++i) a[i] = arow[i];
            unsigned long long b[4];
            const unsigned long long* brow =
                reinterpret_cast<const unsigned long long*>(&Bs[kk * BN]) + tx * 4;
            #pragma unroll
            for (int j = 0; j < 4; ++j) b[j] = brow[j];
            #pragma unroll
            for (int i = 0; i < 8; ++i)
                #pragma unroll
                for (int j = 0; j < 4; ++j)
                    acc[i][j] = fma2(a[i], b[j], acc[i][j]);
        }
        __syncthreads();
    }

    #pragma unroll
    for (int i = 0; i < 8; ++i) {
        const int o = o0 + ty * 8 + i;
        const float bvv = __ldg(&bias[o]);
        float* orow = &Ob[(size_t)o * P + p0 + tx * 8];
        #pragma unroll
        for (int j = 0; j < 4; ++j) {
            float lo, hi;
            unpack2(acc[i][j], lo, hi);
            float2 r;
            r.x = fmaxf(lo + bvv, 0.0f);
            r.y = fmaxf(hi + bvv, 0.0f);
            *reinterpret_cast<float2*>(&orow[2 * j]) = r;
        }
    }
}

// ============================================================================
// Attention fallback (guarded): scores + softmax
// ============================================================================
__global__ __launch_bounds__(256)
void attn_softmax_kernel(const float* __restrict__ alpha)
{
    if (__ldg(alpha) == 0.0f) return;

    __shared__ float e1col[DCH];
    __shared__ float red[256];
    const int tid = threadIdx.x;

    for (int row = blockIdx.x; row < NB * HWP; row += gridDim.x) {
        const int n = row >> 12;
        const int i = row & (HWP - 1);
        const float* e1n = g_e1 + (size_t)n * DCH * HWP;
        const float* e2n = g_e2 + (size_t)n * DCH * HWP;
        float* arow = g_attn + (size_t)n * HWP * HWP + (size_t)i * HWP;

        e1col[tid] = e1n[(size_t)tid * HWP + i];
        __syncthreads();

        float sc[16];
        float mx = -3.4e38f;
        #pragma unroll 1
        for (int jj = 0; jj < 16; ++jj) {
            const int j = jj * 256 + tid;
            float s = 0.0f;
            for (int d = 0; d < DCH; ++d) s += e1col[d] * e2n[(size_t)d * HWP + j];
            sc[jj] = s;
            mx = fmaxf(mx, s);
        }
        red[tid] = mx; __syncthreads();
        for (int s = 128; s > 0; s >>= 1) {
            if (tid < s) red[tid] = fmaxf(red[tid], red[tid + s]);
            __syncthreads();
        }
        mx = red[0]; __syncthreads();

        float sum = 0.0f;
        #pragma unroll
        for (int jj = 0; jj < 16; ++jj) { sc[jj] = expf(sc[jj] - mx); sum += sc[jj]; }
        red[tid] = sum; __syncthreads();
        for (int s = 128; s > 0; s >>= 1) {
            if (tid < s) red[tid] += red[tid + s];
            __syncthreads();
        }
        const float inv = 1.0f / red[0];
        __syncthreads();

        #pragma unroll
        for (int jj = 0; jj < 16; ++jj) arow[jj * 256 + tid] = sc[jj] * inv;
        __syncthreads();
    }
}

// ============================================================================
// Attention fallback bmm (guarded)
// ============================================================================
__global__ __launch_bounds__(256)
void bmm_alpha_kernel(const float* __restrict__ x, float* __restrict__ out,
                      const float* __restrict__ alpha_p)
{
    const float alpha = __ldg(alpha_p);
    if (alpha == 0.0f) return;

    __shared__ float xs[HWP];
    const int tid = threadIdx.x;

    for (int row = blockIdx.x; row < NB * CCH; row += gridDim.x) {
        const int n = row >> 11;
        const int c = row & (CCH - 1);
        const float* xr = x + ((size_t)n * CCH + c) * HWP;
        const float* an = g_attn + (size_t)n * HWP * HWP;
        float* orow = out + ((size_t)n * CCH + c) * HWP;

        for (int j = tid; j < HWP; j += 256) xs[j] = xr[j];
        __syncthreads();

        for (int i = tid; i < HWP; i += 256) {
            float acc = 0.0f;
            const float* ai = an + (size_t)i * HWP;
            for (int j = 0; j < HWP; ++j) acc += xs[j] * ai[j];
            orow[i] += alpha * acc;
        }
        __syncthreads();
    }
}

// ============================================================================
// launch  (7 launches/iter; fp16 GEMM at global index 5 for ncu -s 5 -c 1)
// ============================================================================
extern "C" void kernel_launch(void* const* d_in, const int* in_sizes, int n_in,
                              void* d_out, int out_size)
{
    const float* x     = (const float*)d_in[0];
    const float* w1    = (const float*)d_in[1];
    const float* b1    = (const float*)d_in[2];
    const float* w2    = (const float*)d_in[3];
    const float* b2    = (const float*)d_in[4];
    const float* w3    = (const float*)d_in[5];
    const float* b3    = (const float*)d_in[6];
    const float* alpha = (const float*)d_in[7];
    float* out = (float*)d_out;

    float *e1p = nullptr, *e2p = nullptr;
    __half *w3h = nullptr, *xth = nullptr;
    cudaGetSymbolAddress((void**)&e1p, g_e1);
    cudaGetSymbolAddress((void**)&e2p, g_e2);
    cudaGetSymbolAddress((void**)&w3h, g_w3h);
    cudaGetSymbolAddress((void**)&xth, g_xth);

    static bool attr_done = false;
    if (!attr_done) {
        cudaFuncSetAttribute(gemm_f16_bias_relu,
                             cudaFuncAttributeMaxDynamicSharedMemorySize,
                             GEMM_DSMEM);
        attr_done = true;
    }

    // 0: X -> fp16 transposed [n][p][k]
    xpose_half_kernel<<<dim3(HWP / 32, CCH / 64, NB), 256>>>(x, xth);
    // 1: W3 -> fp16
    cvt_half_kernel<<<2048, 256>>>((const float4*)w3, (uint2*)w3h,
                                   CCH * CCH / 4);
    // 2-4: guarded attention path (early-exit on alpha == 0)
    gemm_bias_relu<<<dim3(HWP / BN, DCH / BM, NB), 256>>>(
        w1, x, b1, e1p, DCH, CCH, HWP, alpha);
    gemm_bias_relu<<<dim3(HWP / BN, DCH / BM, NB), 256>>>(
        w2, x, b2, e2p, DCH, CCH, HWP, alpha);
    attn_softmax_kernel<<<2048, 256>>>(alpha);
    // 5: assembly = relu(w3 @ x + b3) -> d_out  (fp16 tensor cores)
    gemm_f16_bias_relu<<<dim3(HWP / HTN, CCH / HTM, NB), 256, GEMM_DSMEM>>>(
        w3h, xth, b3, out);
    // 6: guarded bmm (out += alpha * x @ attn^T)
    bmm_alpha_kernel<<<1024, 256>>>(x, out, alpha);
}

// round 8
// speedup vs baseline: 6.2960x; 1.5183x over previous
#include <cuda_runtime.h>
#include <cuda_bf16.h>
#include <cuda_fp16.h>
#include <cstdint>

// ============================================================================
// NonLocalPositionAttention
//   y = alpha * (x @ softmax(e1^T e2)^T) + relu(w3 @ x + b3)
// alpha == 0 for benchmark inputs -> y == relu(w3 @ x + b3).
// Assembly GEMM: mma.sync m16n8k16 fp16 over pre-converted operands
// (W3 -> fp16 [o][k]; X -> fp16 transposed [n][p][k]), cp.async 3-stage ring.
// R8: 128x128 CTA tile, 2 CTAs/SM so barrier/wait overhead of one CTA is
// hidden behind the other CTA's HMMA stream. Attention branch guarded.
// ============================================================================

#define NB   4
#define CCH  2048
#define DCH  256
#define HWP  4096

// ---- scratch ---------------------------------------------------------------
__device__ float  g_e1[(size_t)NB * DCH * HWP];
__device__ float  g_e2[(size_t)NB * DCH * HWP];
__device__ float  g_attn[(size_t)NB * HWP * HWP];
__device__ __half g_w3h[(size_t)CCH * CCH];           // fp16 W3 [o][k]
__device__ __half g_xth[(size_t)NB * HWP * CCH];      // fp16 X^T [n][p][k]

// ============================================================================
// helpers
// ============================================================================
__device__ __forceinline__ uint32_t smem_u32(const void* p) {
    uint32_t a;
    asm("{ .reg .u64 t; cvta.to.shared.u64 t, %1; cvt.u32.u64 %0, t; }"
        : "=r"(a) : "l"(p));
    return a;
}
__device__ __forceinline__ void cp_async16(uint32_t dst, const void* src) {
    asm volatile("cp.async.cg.shared.global [%0], [%1], 16;"
                 :: "r"(dst), "l"(src) : "memory");
}
#define CP_COMMIT() asm volatile("cp.async.commit_group;" ::: "memory")
#define CP_WAIT1()  asm volatile("cp.async.wait_group 1;" ::: "memory")

__device__ __forceinline__ void mma_f16(float* d, const uint32_t* a,
                                        const uint32_t* b) {
    asm volatile(
        "mma.sync.aligned.m16n8k16.row.col.f32.f16.f16.f32 "
        "{%0,%1,%2,%3}, {%4,%5,%6,%7}, {%8,%9}, {%0,%1,%2,%3};"
        : "+f"(d[0]), "+f"(d[1]), "+f"(d[2]), "+f"(d[3])
        : "r"(a[0]), "r"(a[1]), "r"(a[2]), "r"(a[3]), "r"(b[0]), "r"(b[1]));
}

// ============================================================================
// pre-pass 1: X [n][c][p] fp32 -> X^T [n][p][c] fp16  (tiled transpose)
// tile: 64 c x 32 p
// ============================================================================
__global__ void __launch_bounds__(256)
xpose_half_kernel(const float* __restrict__ x, __half* __restrict__ xt)
{
    __shared__ float t[32][65];   // [p_local][c_local]
    const int n  = blockIdx.z;
    const int c0 = blockIdx.y * 64;
    const int p0 = blockIdx.x * 32;
    const int tid = threadIdx.x;

    const float* xb = x + (size_t)n * CCH * HWP;
    __half* xtb = xt + (size_t)n * HWP * CCH;

    {
        const int p_l = tid & 31;
        #pragma unroll
        for (int i = 0; i < 8; ++i) {
            const int c_l = (tid >> 5) + i * 8;
            t[p_l][c_l] = xb[(size_t)(c0 + c_l) * HWP + p0 + p_l];
        }
    }
    __syncthreads();
    {
        const int cp = tid & 31;            // half2 pair index (c), 0..31
        #pragma unroll
        for (int i = 0; i < 4; ++i) {
            const int p_l = (tid >> 5) + i * 8;   // 0..31
            __half2 v = __floats2half2_rn(t[p_l][2 * cp], t[p_l][2 * cp + 1]);
            *reinterpret_cast<__half2*>(
                &xtb[(size_t)(p0 + p_l) * CCH + c0 + 2 * cp]) = v;
        }
    }
}

// ============================================================================
// pre-pass 2: W3 fp32 -> fp16 (layout preserved)
// ============================================================================
__global__ void __launch_bounds__(256)
cvt_half_kernel(const float4* __restrict__ src, uint2* __restrict__ dst, int n4)
{
    for (int i = blockIdx.x * blockDim.x + threadIdx.x; i < n4;
         i += gridDim.x * blockDim.x) {
        const float4 v = src[i];
        __half2 lo = __floats2half2_rn(v.x, v.y);
        __half2 hi = __floats2half2_rn(v.z, v.w);
        uint2 o;
        o.x = *reinterpret_cast<uint32_t*>(&lo);
        o.y = *reinterpret_cast<uint32_t*>(&hi);
        dst[i] = o;
    }
}

// ============================================================================
// fp16 tensor-core GEMM + bias + relu:
//   out[n,o,p] = relu( sum_c W[o,c] * X[n,c,p] + bias[o] )
// CTA tile 128(m) x 128(n) x 32(k); 256 threads = 8 warps (2m x 4n);
// warp tile 64x32. A/B smem rows pitch 20 words (32 fp16 + pad) ->
// conflict-free fragment loads (banks {20g mod 32} + tig cover 0..31).
// cp.async cg 3-stage ring, 1 syncthreads/slab, 2 CTAs per SM.
// ============================================================================
#define HTM 128
#define HTN 128
#define HTK 32
#define H_NSLABS (CCH / HTK)                 // 64
#define HPITCH_B 80                          // bytes per smem row (32 fp16 + pad)
#define A_STAGE (HTM * HPITCH_B)             // 10240
#define B_STAGE (HTN * HPITCH_B)             // 10240
#define STAGE_B (A_STAGE + B_STAGE)          // 20480
#define GEMM_DSMEM (3 * STAGE_B)             // 61440

__global__ void __launch_bounds__(256, 2)
gemm_f16_bias_relu(const __half* __restrict__ Wh, const __half* __restrict__ Xth,
                   const float* __restrict__ bias, float* __restrict__ out)
{
    extern __shared__ char smem[];
    const uint32_t smem_base = smem_u32(smem);

    const int tid  = threadIdx.x;
    const int wid  = tid >> 5;
    const int lane = tid & 31;
    const int g    = lane >> 2;
    const int tig  = lane & 3;
    const int wm   = wid >> 2;     // 0..1
    const int wn   = wid & 3;      // 0..3

    const int n  = blockIdx.z;
    const int o0 = blockIdx.y * HTM;
    const int p0 = blockIdx.x * HTN;
    const __half* Xb = Xth + (size_t)n * HWP * CCH;
    float*        Ob = out + (size_t)n * CCH * HWP;

    float acc[4][4][4];
    #pragma unroll
    for (int mi = 0; mi < 4; ++mi)
        #pragma unroll
        for (int ni = 0; ni < 4; ++ni)
            #pragma unroll
            for (int q = 0; q < 4; ++q) acc[mi][ni][q] = 0.0f;

    // cp.async mappings (16B chunks of 8 fp16):
    //   A: 512 chunks: c = tid + j*256 (j<2): row=c>>2 (0..127), cw=c&3
    //   B: 512 chunks: same mapping over Xb rows
    const int cp_row = tid >> 2, cp_cw = tid & 3;

    #define ISSUE_SLAB(S, BUF) do {                                           \
        const int _k0 = (S) * HTK;                                            \
        const uint32_t _dA = smem_base + (BUF) * STAGE_B;                     \
        const uint32_t _dB = _dA + A_STAGE;                                   \
        _Pragma("unroll")                                                     \
        for (int j = 0; j < 2; ++j) {                                         \
            const int row = cp_row + j * 64;                                  \
            cp_async16(_dA + row * HPITCH_B + cp_cw * 16,                     \
                       &Wh[(size_t)(o0 + row) * CCH + _k0 + cp_cw * 8]);      \
        }                                                                     \
        _Pragma("unroll")                                                     \
        for (int j = 0; j < 2; ++j) {                                         \
            const int row = cp_row + j * 64;                                  \
            cp_async16(_dB + row * HPITCH_B + cp_cw * 16,                     \
                       &Xb[(size_t)(p0 + row) * CCH + _k0 + cp_cw * 8]);      \
        }                                                                     \
    } while (0)

    ISSUE_SLAB(0, 0); CP_COMMIT();
    ISSUE_SLAB(1, 1); CP_COMMIT();

    for (int s = 0; s < H_NSLABS; ++s) {
        CP_WAIT1();
        __syncthreads();
        if (s + 2 < H_NSLABS) ISSUE_SLAB(s + 2, (s + 2) % 3);
        CP_COMMIT();

        const uint32_t* As = reinterpret_cast<const uint32_t*>(
            smem + (s % 3) * STAGE_B);
        const uint32_t* Bs = reinterpret_cast<const uint32_t*>(
            smem + (s % 3) * STAGE_B + A_STAGE);

        #pragma unroll
        for (int ks = 0; ks < 2; ++ks) {
            const int kw = ks * 8 + tig;      // word index within 20-word row
            uint32_t a[4][4];
            #pragma unroll
            for (int mi = 0; mi < 4; ++mi) {
                const int m = wm * 64 + mi * 16;
                a[mi][0] = As[(m + g) * 20 + kw];
                a[mi][1] = As[(m + 8 + g) * 20 + kw];
                a[mi][2] = As[(m + g) * 20 + kw + 4];
                a[mi][3] = As[(m + 8 + g) * 20 + kw + 4];
            }
            uint32_t b[4][2];
            #pragma unroll
            for (int ni = 0; ni < 4; ++ni) {
                const int col = wn * 32 + ni * 8 + g;
                b[ni][0] = Bs[col * 20 + kw];
                b[ni][1] = Bs[col * 20 + kw + 4];
            }
            #pragma unroll
            for (int mi = 0; mi < 4; ++mi)
                #pragma unroll
                for (int ni = 0; ni < 4; ++ni)
                    mma_f16(acc[mi][ni], a[mi], b[ni]);
        }
    }

    // ---- epilogue: bias + relu -> GMEM ----
    #pragma unroll
    for (int mi = 0; mi < 4; ++mi) {
        const int row_lo = o0 + wm * 64 + mi * 16 + g;
        const int row_hi = row_lo + 8;
        const float blo = __ldg(&bias[row_lo]);
        const float bhi = __ldg(&bias[row_hi]);
        float* plo = &Ob[(size_t)row_lo * HWP + p0 + wn * 32 + tig * 2];
        float* phi = &Ob[(size_t)row_hi * HWP + p0 + wn * 32 + tig * 2];
        #pragma unroll
        for (int ni = 0; ni < 4; ++ni) {
            float2 vlo, vhi;
            vlo.x = fmaxf(acc[mi][ni][0] + blo, 0.0f);
            vlo.y = fmaxf(acc[mi][ni][1] + blo, 0.0f);
            vhi.x = fmaxf(acc[mi][ni][2] + bhi, 0.0f);
            vhi.y = fmaxf(acc[mi][ni][3] + bhi, 0.0f);
            *reinterpret_cast<float2*>(&plo[ni * 8]) = vlo;
            *reinterpret_cast<float2*>(&phi[ni * 8]) = vhi;
        }
    }
}

// ============================================================================
// FFMA2 SGEMM (guarded attention path only: e1/e2)
// ============================================================================
__device__ __forceinline__ unsigned long long pack2(float lo, float hi) {
    unsigned long long r;
    asm("mov.b64 %0, {%1, %2};" : "=l"(r) : "f"(lo), "f"(hi));
    return r;
}
__device__ __forceinline__ void unpack2(unsigned long long v, float& lo, float& hi) {
    asm("mov.b64 {%0, %1}, %2;" : "=f"(lo), "=f"(hi) : "l"(v));
}
__device__ __forceinline__ unsigned long long fma2(unsigned long long a,
                                                   unsigned long long b,
                                                   unsigned long long c) {
    unsigned long long d;
    asm("fma.rn.f32x2 %0, %1, %2, %3;" : "=l"(d) : "l"(a), "l"(b), "l"(c));
    return d;
}

#define BM 128
#define BN 128
#define BK 16
#define FPITCH 130

__global__ __launch_bounds__(256, 2)
void gemm_bias_relu(const float* __restrict__ W, const float* __restrict__ X,
                    const float* __restrict__ bias, float* __restrict__ out,
                    int O, int K, int P, const float* __restrict__ guard)
{
    if (guard != nullptr && __ldg(guard) == 0.0f) return;

    const int n  = blockIdx.z;
    const float* Xb = X  + (size_t)n * K * P;
    float*       Ob = out + (size_t)n * O * P;

    __shared__ unsigned long long As[BK * FPITCH];
    __shared__ float              Bs[BK * BN];

    const int tid = threadIdx.x;
    const int tx  = tid & 15;
    const int ty  = tid >> 4;
    const int o0  = blockIdx.y * BM;
    const int p0  = blockIdx.x * BN;

    unsigned long long acc[8][4];
    #pragma unroll
    for (int i = 0; i < 8; ++i)
        #pragma unroll
        for (int j = 0; j < 4; ++j) acc[i][j] = 0ULL;

    const int wr0 = tid >> 2;
    const int wc0 = (tid & 3) * 4;
    const int xk0 = tid >> 5;
    const int xc0 = (tid & 31) * 4;

    for (int k0 = 0; k0 < K; k0 += BK) {
        #pragma unroll
        for (int l = 0; l < 2; ++l) {
            const int r = wr0 + l * 64;
            const float4 v = *reinterpret_cast<const float4*>(
                &W[(size_t)(o0 + r) * K + k0 + wc0]);
            As[(wc0 + 0) * FPITCH + r] = pack2(v.x, v.x);
            As[(wc0 + 1) * FPITCH + r] = pack2(v.y, v.y);
            As[(wc0 + 2) * FPITCH + r] = pack2(v.z, v.z);
            As[(wc0 + 3) * FPITCH + r] = pack2(v.w, v.w);
        }
        #pragma unroll
        for (int l = 0; l < 2; ++l) {
            const int kk = xk0 + l * 8;
            const float4 v = *reinterpret_cast<const float4*>(
                &Xb[(size_t)(k0 + kk) * P + p0 + xc0]);
            *reinterpret_cast<float4*>(&Bs[kk * BN + xc0]) = v;
        }
        __syncthreads();

        #pragma unroll
        for (int kk = 0; kk < BK; ++kk) {
            unsigned long long a[8];
            const unsigned long long* arow = &As[kk * FPITCH + ty * 8];
            #pragma unroll
            for (int i = 0; i < 8; ++i) a[i] = arow[i];
            unsigned long long b[4];
            const unsigned long long* brow =
                reinterpret_cast<const unsigned long long*>(&Bs[kk * BN]) + tx * 4;
            #pragma unroll
            for (int j = 0; j < 4; ++j) b[j] = brow[j];
            #pragma unroll
            for (int i = 0; i < 8; ++i)
                #pragma unroll
                for (int j = 0; j < 4; ++j)
                    acc[i][j] = fma2(a[i], b[j], acc[i][j]);
        }
        __syncthreads();
    }

    #pragma unroll
    for (int i = 0; i < 8; ++i) {
        const int o = o0 + ty * 8 + i;
        const float bvv = __ldg(&bias[o]);
        float* orow = &Ob[(size_t)o * P + p0 + tx * 8];
        #pragma unroll
        for (int j = 0; j < 4; ++j) {
            float lo, hi;
            unpack2(acc[i][j], lo, hi);
            float2 r;
            r.x = fmaxf(lo + bvv, 0.0f);
            r.y = fmaxf(hi + bvv, 0.0f);
            *reinterpret_cast<float2*>(&orow[2 * j]) = r;
        }
    }
}

// ============================================================================
// Attention fallback (guarded): scores + softmax
// ============================================================================
__global__ __launch_bounds__(256)
void attn_softmax_kernel(const float* __restrict__ alpha)
{
    if (__ldg(alpha) == 0.0f) return;

    __shared__ float e1col[DCH];
    __shared__ float red[256];
    const int tid = threadIdx.x;

    for (int row = blockIdx.x; row < NB * HWP; row += gridDim.x) {
        const int n = row >> 12;
        const int i = row & (HWP - 1);
        const float* e1n = g_e1 + (size_t)n * DCH * HWP;
        const float* e2n = g_e2 + (size_t)n * DCH * HWP;
        float* arow = g_attn + (size_t)n * HWP * HWP + (size_t)i * HWP;

        e1col[tid] = e1n[(size_t)tid * HWP + i];
        __syncthreads();

        float sc[16];
        float mx = -3.4e38f;
        #pragma unroll 1
        for (int jj = 0; jj < 16; ++jj) {
            const int j = jj * 256 + tid;
            float s = 0.0f;
            for (int d = 0; d < DCH; ++d) s += e1col[d] * e2n[(size_t)d * HWP + j];
            sc[jj] = s;
            mx = fmaxf(mx, s);
        }
        red[tid] = mx; __syncthreads();
        for (int s = 128; s > 0; s >>= 1) {
            if (tid < s) red[tid] = fmaxf(red[tid], red[tid + s]);
            __syncthreads();
        }
        mx = red[0]; __syncthreads();

        float sum = 0.0f;
        #pragma unroll
        for (int jj = 0; jj < 16; ++jj) { sc[jj] = expf(sc[jj] - mx); sum += sc[jj]; }
        red[tid] = sum; __syncthreads();
        for (int s = 128; s > 0; s >>= 1) {
            if (tid < s) red[tid] += red[tid + s];
            __syncthreads();
        }
        const float inv = 1.0f / red[0];
        __syncthreads();

        #pragma unroll
        for (int jj = 0; jj < 16; ++jj) arow[jj * 256 + tid] = sc[jj] * inv;
        __syncthreads();
    }
}

// ============================================================================
// Attention fallback bmm (guarded)
// ============================================================================
__global__ __launch_bounds__(256)
void bmm_alpha_kernel(const float* __restrict__ x, float* __restrict__ out,
                      const float* __restrict__ alpha_p)
{
    const float alpha = __ldg(alpha_p);
    if (alpha == 0.0f) return;

    __shared__ float xs[HWP];
    const int tid = threadIdx.x;

    for (int row = blockIdx.x; row < NB * CCH; row += gridDim.x) {
        const int n = row >> 11;
        const int c = row & (CCH - 1);
        const float* xr = x + ((size_t)n * CCH + c) * HWP;
        const float* an = g_attn + (size_t)n * HWP * HWP;
        float* orow = out + ((size_t)n * CCH + c) * HWP;

        for (int j = tid; j < HWP; j += 256) xs[j] = xr[j];
        __syncthreads();

        for (int i = tid; i < HWP; i += 256) {
            float acc = 0.0f;
            const float* ai = an + (size_t)i * HWP;
            for (int j = 0; j < HWP; ++j) acc += xs[j] * ai[j];
            orow[i] += alpha * acc;
        }
        __syncthreads();
    }
}

// ============================================================================
// launch
// ============================================================================
extern "C" void kernel_launch(void* const* d_in, const int* in_sizes, int n_in,
                              void* d_out, int out_size)
{
    const float* x     = (const float*)d_in[0];
    const float* w1    = (const float*)d_in[1];
    const float* b1    = (const float*)d_in[2];
    const float* w2    = (const float*)d_in[3];
    const float* b2    = (const float*)d_in[4];
    const float* w3    = (const float*)d_in[5];
    const float* b3    = (const float*)d_in[6];
    const float* alpha = (const float*)d_in[7];
    float* out = (float*)d_out;

    float *e1p = nullptr, *e2p = nullptr;
    __half *w3h = nullptr, *xth = nullptr;
    cudaGetSymbolAddress((void**)&e1p, g_e1);
    cudaGetSymbolAddress((void**)&e2p, g_e2);
    cudaGetSymbolAddress((void**)&w3h, g_w3h);
    cudaGetSymbolAddress((void**)&xth, g_xth);

    static bool attr_done = false;
    if (!attr_done) {
        cudaFuncSetAttribute(gemm_f16_bias_relu,
                             cudaFuncAttributeMaxDynamicSharedMemorySize,
                             GEMM_DSMEM);
        attr_done = true;
    }

    // 0: X -> fp16 transposed [n][p][k]
    xpose_half_kernel<<<dim3(HWP / 32, CCH / 64, NB), 256>>>(x, xth);
    // 1: W3 -> fp16
    cvt_half_kernel<<<2048, 256>>>((const float4*)w3, (uint2*)w3h,
                                   CCH * CCH / 4);
    // 2-4: guarded attention path (early-exit on alpha == 0)
    gemm_bias_relu<<<dim3(HWP / BN, DCH / BM, NB), 256>>>(
        w1, x, b1, e1p, DCH, CCH, HWP, alpha);
    gemm_bias_relu<<<dim3(HWP / BN, DCH / BM, NB), 256>>>(
        w2, x, b2, e2p, DCH, CCH, HWP, alpha);
    attn_softmax_kernel<<<2048, 256>>>(alpha);
    // 5: assembly = relu(w3 @ x + b3) -> d_out  (fp16 tensor cores, occ=2)
    gemm_f16_bias_relu<<<dim3(HWP / HTN, CCH / HTM, NB), 256, GEMM_DSMEM>>>(
        w3h, xth, b3, out);
    // 6: guarded bmm (out += alpha * x @ attn^T)
    bmm_alpha_kernel<<<1024, 256>>>(x, out, alpha);
}